// round 9
// baseline (speedup 1.0000x reference)
#include <cuda_runtime.h>

// out[b] = ||x_dot[b]||^2 + (x_dot[b]^T W x[b])^2
//
// t[b] = sum_{j,k} x_dot[b,j] * W[j,k] * x[b,k] is fully bilinear, so we tile
// over (batch, k(=n), j) and sum deterministic per-tile partials.
//
// Kernel 1: tiled fp32 GEMM U = x_dot @ W (M=128, N=128 per CTA, K-slice=64),
//           fused epilogue: partial_t = sum_n U[b,n] * x[b,n] over the CTA's
//           n-tile, reduced across the 16 threads sharing a row, written to a
//           unique (tile, b) slot (no atomics -> deterministic).
// Kernel 2: out[b] = ||x_dot[b]||^2 + (sum of 32 partials)^2.

#define BM 128
#define BN 128
#define KSL 64
#define BK 32
#define LDSS 132   // 128 + 4 pad (keeps float4 smem loads 16B-aligned)

// 32 (n-tile, j-slice) tiles x 1024 batch rows of fp32 partials (128 KB scratch)
__device__ float g_partial[32 * 1024];

__global__ __launch_bounds__(256, 2)
void stm_gemm(const float* __restrict__ x,
              const float* __restrict__ xdot,
              const float* __restrict__ W) {
    __shared__ float As[BK * LDSS];   // As[k][m]  (x_dot tile, transposed)
    __shared__ float Bs[BK * LDSS];   // Bs[k][n]  (W tile, natural)

    const int tid = threadIdx.x;
    const int tx  = tid & 15;         // n micro-tile index (16)
    const int ty  = tid >> 4;         // m micro-tile index (16)
    const int n0  = blockIdx.x * BN;  // gridDim.x = 4
    const int b0  = blockIdx.y * BM;  // gridDim.y = 8
    const int j0  = blockIdx.z * KSL; // gridDim.z = 8

    float acc[8][8];
#pragma unroll
    for (int r = 0; r < 8; r++)
#pragma unroll
        for (int c = 0; c < 8; c++) acc[r][c] = 0.0f;

    for (int ck = 0; ck < KSL; ck += BK) {
        const int jc = j0 + ck;

        // --- stage x_dot[b0:+128, jc:+32] into As, transposed to [k][m] ---
#pragma unroll
        for (int p = 0; p < 4; p++) {
            int idx = tid + p * 256;          // 0..1023 float4s
            int row = idx >> 3;               // 0..127 (batch row)
            int c4  = idx & 7;                // 0..7   (k group of 4)
            float4 v = *(const float4*)(xdot + (size_t)(b0 + row) * 512 + jc + c4 * 4);
            As[(c4 * 4 + 0) * LDSS + row] = v.x;
            As[(c4 * 4 + 1) * LDSS + row] = v.y;
            As[(c4 * 4 + 2) * LDSS + row] = v.z;
            As[(c4 * 4 + 3) * LDSS + row] = v.w;
        }
        // --- stage W[jc:+32, n0:+128] into Bs[k][n] ---
#pragma unroll
        for (int p = 0; p < 4; p++) {
            int idx = tid + p * 256;
            int row = idx >> 5;               // 0..31 (j)
            int c4  = idx & 31;               // 0..31 (n group of 4)
            float4 v = *(const float4*)(W + (size_t)(jc + row) * 512 + n0 + c4 * 4);
            *(float4*)(Bs + row * LDSS + c4 * 4) = v;
        }
        __syncthreads();

#pragma unroll
        for (int kk = 0; kk < BK; kk++) {
            float a[8], b[8];
            *(float4*)(a)     = *(const float4*)(As + kk * LDSS + ty * 8);
            *(float4*)(a + 4) = *(const float4*)(As + kk * LDSS + ty * 8 + 4);
            *(float4*)(b)     = *(const float4*)(Bs + kk * LDSS + tx * 8);
            *(float4*)(b + 4) = *(const float4*)(Bs + kk * LDSS + tx * 8 + 4);
#pragma unroll
            for (int r = 0; r < 8; r++)
#pragma unroll
                for (int c = 0; c < 8; c++)
                    acc[r][c] = fmaf(a[r], b[c], acc[r][c]);
        }
        __syncthreads();
    }

    // --- fused epilogue: partial bilinear form over this n-tile ---
    const int tileIdx = blockIdx.x * 8 + blockIdx.z;   // 0..31
#pragma unroll
    for (int r = 0; r < 8; r++) {
        int b = b0 + ty * 8 + r;
        const float* xr = x + (size_t)b * 512 + n0 + tx * 8;
        float4 x0 = *(const float4*)(xr);
        float4 x1 = *(const float4*)(xr + 4);
        float s = acc[r][0] * x0.x + acc[r][1] * x0.y
                + acc[r][2] * x0.z + acc[r][3] * x0.w
                + acc[r][4] * x1.x + acc[r][5] * x1.y
                + acc[r][6] * x1.z + acc[r][7] * x1.w;
        // reduce across the 16 tx-threads of this row (xor <16 stays in group)
        s += __shfl_xor_sync(0xffffffffu, s, 8);
        s += __shfl_xor_sync(0xffffffffu, s, 4);
        s += __shfl_xor_sync(0xffffffffu, s, 2);
        s += __shfl_xor_sync(0xffffffffu, s, 1);
        if (tx == 0) g_partial[tileIdx * 1024 + b] = s;
    }
}

__global__ __launch_bounds__(256)
void stm_finalize(const float* __restrict__ xdot, float* __restrict__ out) {
    int b    = (blockIdx.x * blockDim.x + threadIdx.x) >> 5;  // one warp per row
    int lane = threadIdx.x & 31;
    if (b >= 1024) return;

    const float4* xr = (const float4*)(xdot + (size_t)b * 512);
    float n2 = 0.0f;
#pragma unroll
    for (int i = 0; i < 4; i++) {
        float4 v = xr[lane + 32 * i];
        n2 += v.x * v.x + v.y * v.y + v.z * v.z + v.w * v.w;
    }
    float tp = g_partial[lane * 1024 + b];   // 32 partials, one per lane
#pragma unroll
    for (int o = 16; o > 0; o >>= 1) {
        n2 += __shfl_xor_sync(0xffffffffu, n2, o);
        tp += __shfl_xor_sync(0xffffffffu, tp, o);
    }
    if (lane == 0) out[b] = n2 + tp * tp;
}

extern "C" void kernel_launch(void* const* d_in, const int* in_sizes, int n_in,
                              void* d_out, int out_size) {
    const float* x    = (const float*)d_in[0];   // [1024, 512]
    const float* xdot = (const float*)d_in[1];   // [1024, 512]
    const float* W    = (const float*)d_in[2];   // [512, 512]
    float* out = (float*)d_out;                  // [1024]

    dim3 grid(4, 8, 8);   // (n-tiles, b-tiles, j-slices) = 256 CTAs
    stm_gemm<<<grid, 256>>>(x, xdot, W);
    stm_finalize<<<128, 256>>>(xdot, out);
}

// round 11
// speedup vs baseline: 1.1774x; 1.1774x over previous
#include <cuda_runtime.h>
#include <cuda_bf16.h>
#include <cstdint>

// out[b] = ||xdot[b]||^2 + (xdot[b]^T W x[b])^2
//
// Tensor-core path via warp-level mma.sync (plain compute_103 PTX; tcgen05 is
// rejected by the harness's compute_103 PTX target). U = xdot @ W as bf16
// hi/lo split (U ~= Ah*Bh + Ah*Bl + Al*Bh, fp32 accum, ~2^-17 eff. precision),
// then t[b] = sum_n U[b,n] x[b,n] in an fp32 epilogue.
//
//  k1: xdot -> (Ah, Al) bf16 + fused ||xdot||^2
//  k2: W    -> transposed (Bh, Bl) bf16 ([n][j], K-contiguous = mma col-major B)
//  k3: HMMA GEMM, CTA tile 128x64, k-split 2 (K=256/CTA), cp.async double
//      buffer, fused bilinear epilogue -> deterministic per-(ntile,kz) partials
//  k4: out[b] = norm[b] + (sum of 16 partials)^2

#define NB 1024
#define ND 512
#define BM 128
#define BN 64
#define BKC 32            // k per chunk
#define KS 256            // k per CTA (8 chunks)
#define LDA 40            // bf16 elems per smem row (32 + 4 pad -> 80B, conflict-free ldmatrix)
#define LDU 66            // fp32 elems per Us row

// ---------------- scratch ----------------
__device__ __nv_bfloat16 g_Ah[NB * ND];
__device__ __nv_bfloat16 g_Al[NB * ND];
__device__ __nv_bfloat16 g_Bh[ND * ND];   // [n][j] = hi(W[j][n])
__device__ __nv_bfloat16 g_Bl[ND * ND];
__device__ float g_norm[NB];
__device__ float g_partial[16 * NB];

// smem stage layout (bytes): Ah 10240 | Al 10240 | Bh 5120 | Bl 5120 = 30720
#define ST_AH 0
#define ST_AL 10240
#define ST_BH 20480
#define ST_BL 25600
#define STAGE 30720
#define SMEM_MMA (2 * STAGE)   // 61440; Us (128*66*4=33792) reuses buf0 region

// ---------------- PTX helpers ----------------
__device__ __forceinline__ uint32_t smem_u32(const void* p) {
    uint32_t a;
    asm("{ .reg .u64 t; cvta.to.shared.u64 t, %1; cvt.u32.u64 %0, t; }"
        : "=r"(a) : "l"(p));
    return a;
}
__device__ __forceinline__ void cpa16(uint32_t dst, const void* src) {
    asm volatile("cp.async.cg.shared.global [%0], [%1], 16;\n" :: "r"(dst), "l"(src));
}
#define CP_COMMIT() asm volatile("cp.async.commit_group;\n" ::: "memory")
#define CP_WAIT(n)  asm volatile("cp.async.wait_group %0;\n" :: "n"(n) : "memory")

__device__ __forceinline__ void ldsm_x4(uint32_t& r0, uint32_t& r1,
                                        uint32_t& r2, uint32_t& r3, uint32_t addr) {
    asm volatile("ldmatrix.sync.aligned.m8n8.x4.shared.b16 {%0,%1,%2,%3}, [%4];"
                 : "=r"(r0), "=r"(r1), "=r"(r2), "=r"(r3) : "r"(addr));
}
__device__ __forceinline__ void mma16816(float* c, const uint32_t* a, const uint32_t* b) {
    asm volatile("mma.sync.aligned.m16n8k16.row.col.f32.bf16.bf16.f32 "
                 "{%0,%1,%2,%3}, {%4,%5,%6,%7}, {%8,%9}, {%0,%1,%2,%3};"
                 : "+f"(c[0]), "+f"(c[1]), "+f"(c[2]), "+f"(c[3])
                 : "r"(a[0]), "r"(a[1]), "r"(a[2]), "r"(a[3]), "r"(b[0]), "r"(b[1]));
}

// ---------------- k1: xdot -> Ah/Al + row norms ----------------
__global__ __launch_bounds__(256)
void stm_cvt_a(const float* __restrict__ xd) {
    int wid = threadIdx.x >> 5, lane = threadIdx.x & 31;
    int b = blockIdx.x * 8 + wid;
    const float4* xr = (const float4*)(xd + (size_t)b * ND);
    __nv_bfloat162* ah = (__nv_bfloat162*)(g_Ah + (size_t)b * ND);
    __nv_bfloat162* al = (__nv_bfloat162*)(g_Al + (size_t)b * ND);
    float n2 = 0.0f;
#pragma unroll
    for (int p = 0; p < 4; p++) {
        int q = lane + 32 * p;
        float4 v = xr[q];
        n2 += v.x * v.x + v.y * v.y + v.z * v.z + v.w * v.w;
        __nv_bfloat16 hx = __float2bfloat16(v.x), hy = __float2bfloat16(v.y);
        __nv_bfloat16 hz = __float2bfloat16(v.z), hw = __float2bfloat16(v.w);
        ah[q * 2 + 0] = __halves2bfloat162(hx, hy);
        ah[q * 2 + 1] = __halves2bfloat162(hz, hw);
        al[q * 2 + 0] = __halves2bfloat162(__float2bfloat16(v.x - __bfloat162float(hx)),
                                           __float2bfloat16(v.y - __bfloat162float(hy)));
        al[q * 2 + 1] = __halves2bfloat162(__float2bfloat16(v.z - __bfloat162float(hz)),
                                           __float2bfloat16(v.w - __bfloat162float(hw)));
    }
#pragma unroll
    for (int o = 16; o > 0; o >>= 1) n2 += __shfl_xor_sync(0xffffffffu, n2, o);
    if (lane == 0) g_norm[b] = n2;
}

// ---------------- k2: W -> transposed Bh/Bl ----------------
__global__ __launch_bounds__(256)
void stm_cvt_b(const float* __restrict__ W) {
    __shared__ float s[32][33];
    int tx = threadIdx.x & 31, ty = threadIdx.x >> 5;
    int j0 = blockIdx.y * 32, n0 = blockIdx.x * 32;
#pragma unroll
    for (int i = 0; i < 4; i++) {
        int r = ty + 8 * i;
        s[r][tx] = W[(size_t)(j0 + r) * ND + n0 + tx];
    }
    __syncthreads();
#pragma unroll
    for (int i = 0; i < 4; i++) {
        int r = ty + 8 * i;                 // local n
        float v = s[tx][r];                 // = W[j0+tx][n0+r]
        __nv_bfloat16 h = __float2bfloat16(v);
        size_t o = (size_t)(n0 + r) * ND + j0 + tx;
        g_Bh[o] = h;
        g_Bl[o] = __float2bfloat16(v - __bfloat162float(h));
    }
}

// ---------------- k3: HMMA GEMM + fused bilinear epilogue ----------------
__device__ __forceinline__ void load_chunk(uint32_t sb, int stage, int b0, int n0,
                                           int kc, int tid) {
    uint32_t base = sb + stage * STAGE;
#pragma unroll
    for (int p = 0; p < 2; p++) {
        int idx = tid + p * 256;            // 0..511
        int row = idx >> 2, c = idx & 3;    // row 0..127, 16B chunk 0..3
        uint32_t d = base + row * 80 + c * 16;
        size_t off = (size_t)(b0 + row) * ND + kc + c * 8;
        cpa16(d + ST_AH, g_Ah + off);
        cpa16(d + ST_AL, g_Al + off);
    }
    {
        int row = tid >> 2, c = tid & 3;    // row 0..63
        uint32_t d = base + row * 80 + c * 16;
        size_t off = (size_t)(n0 + row) * ND + kc + c * 8;
        cpa16(d + ST_BH, g_Bh + off);
        cpa16(d + ST_BL, g_Bl + off);
    }
}

__global__ __launch_bounds__(256, 1)
void stm_mma(const float* __restrict__ x) {
    extern __shared__ __align__(128) char smem[];
    uint32_t sb = smem_u32(smem);
    const int tid = threadIdx.x, wid = tid >> 5, lane = tid & 31;
    const int wm = wid & 3, wn = wid >> 2;       // warp tile (32m x 32n)
    const int n0 = blockIdx.x * BN;
    const int b0 = blockIdx.y * BM;
    const int kz = blockIdx.z;
    const int kbase = kz * KS;

    float c[2][4][4];                             // [m16 blk][n8 blk][reg]
#pragma unroll
    for (int i = 0; i < 2; i++)
#pragma unroll
        for (int j = 0; j < 4; j++)
#pragma unroll
            for (int r = 0; r < 4; r++) c[i][j][r] = 0.0f;

    load_chunk(sb, 0, b0, n0, kbase, tid);
    CP_COMMIT();

    for (int ch = 0; ch < 8; ch++) {
        if (ch < 7) {
            load_chunk(sb, (ch + 1) & 1, b0, n0, kbase + (ch + 1) * BKC, tid);
            CP_COMMIT();
            CP_WAIT(1);
        } else {
            CP_WAIT(0);
        }
        __syncthreads();

        uint32_t st = sb + (ch & 1) * STAGE;
#pragma unroll
        for (int kk = 0; kk < BKC; kk += 16) {
            // A fragments (Ah, Al), 2 m16 blocks
            uint32_t ah[2][4], al[2][4];
#pragma unroll
            for (int mb = 0; mb < 2; mb++) {
                int row = wm * 32 + mb * 16 + (lane & 15);
                uint32_t off = row * 80 + (kk + (lane >> 4) * 8) * 2;
                ldsm_x4(ah[mb][0], ah[mb][1], ah[mb][2], ah[mb][3], st + ST_AH + off);
                ldsm_x4(al[mb][0], al[mb][1], al[mb][2], al[mb][3], st + ST_AL + off);
            }
            // B fragments (Bh, Bl), 4 n8 blocks (2 per x4)
            uint32_t bh[4][2], bl[4][2];
#pragma unroll
            for (int np = 0; np < 2; np++) {
                int row = wn * 32 + np * 16 + (lane & 7) + ((lane >> 4) << 3);
                uint32_t off = row * 80 + (kk + ((lane >> 3) & 1) * 8) * 2;
                ldsm_x4(bh[2 * np][0], bh[2 * np][1], bh[2 * np + 1][0], bh[2 * np + 1][1],
                        st + ST_BH + off);
                ldsm_x4(bl[2 * np][0], bl[2 * np][1], bl[2 * np + 1][0], bl[2 * np + 1][1],
                        st + ST_BL + off);
            }
#pragma unroll
            for (int mb = 0; mb < 2; mb++)
#pragma unroll
                for (int nb = 0; nb < 4; nb++) {
                    mma16816(c[mb][nb], ah[mb], bh[nb]);
                    mma16816(c[mb][nb], ah[mb], bl[nb]);
                    mma16816(c[mb][nb], al[mb], bh[nb]);
                }
        }
        __syncthreads();
    }

    // ---- epilogue: accumulators -> smem, per-row dot with x ----
    float* Us = (float*)smem;                     // 128 x LDU fp32 (reuses buf0)
#pragma unroll
    for (int mb = 0; mb < 2; mb++) {
        int row = wm * 32 + mb * 16 + (lane >> 2);
#pragma unroll
        for (int nb = 0; nb < 4; nb++) {
            int col = wn * 32 + nb * 8 + (lane & 3) * 2;
            *(float2*)(Us + row * LDU + col)       = make_float2(c[mb][nb][0], c[mb][nb][1]);
            *(float2*)(Us + (row + 8) * LDU + col) = make_float2(c[mb][nb][2], c[mb][nb][3]);
        }
    }
    __syncthreads();

    {
        int row = tid >> 1, half = tid & 1;       // 2 threads per row, 32 cols each
        const float4* xr = (const float4*)(x + (size_t)(b0 + row) * ND + n0 + half * 32);
        const float* ur = Us + row * LDU + half * 32;
        float s = 0.0f;
#pragma unroll
        for (int q = 0; q < 8; q++) {
            float4 v = xr[q];
            s = fmaf(ur[4 * q + 0], v.x, s);
            s = fmaf(ur[4 * q + 1], v.y, s);
            s = fmaf(ur[4 * q + 2], v.z, s);
            s = fmaf(ur[4 * q + 3], v.w, s);
        }
        s += __shfl_xor_sync(0xffffffffu, s, 1);
        if (half == 0)
            g_partial[(blockIdx.x * 2 + kz) * NB + b0 + row] = s;
    }
}

// ---------------- k4: finalize ----------------
__global__ __launch_bounds__(256)
void stm_fin(float* __restrict__ out) {
    int b = blockIdx.x * 256 + threadIdx.x;
    float t = 0.0f;
#pragma unroll
    for (int k = 0; k < 16; k++) t += g_partial[k * NB + b];
    out[b] = g_norm[b] + t * t;
}

// ---------------- launch ----------------
extern "C" void kernel_launch(void* const* d_in, const int* in_sizes, int n_in,
                              void* d_out, int out_size) {
    const float* x    = (const float*)d_in[0];   // [1024, 512]
    const float* xdot = (const float*)d_in[1];   // [1024, 512]
    const float* W    = (const float*)d_in[2];   // [512, 512]
    float* out = (float*)d_out;                  // [1024]

    cudaFuncSetAttribute(stm_mma, cudaFuncAttributeMaxDynamicSharedMemorySize, SMEM_MMA);

    stm_cvt_a<<<128, 256>>>(xdot);
    stm_cvt_b<<<dim3(16, 16), 256>>>(W);
    stm_mma<<<dim3(8, 8, 2), 256, SMEM_MMA>>>(x);
    stm_fin<<<4, 256>>>(out);
}

// round 12
// speedup vs baseline: 1.1794x; 1.0017x over previous
#include <cuda_runtime.h>
#include <cuda_bf16.h>
#include <cstdint>

// out[b] = ||xdot[b]||^2 + (xdot[b]^T W x[b])^2
//
// bf16 hi/lo split HMMA GEMM (U ~= Ah*Bh + Ah*Bl + Al*Bh, fp32 accum), then
// t[b] = sum_n U[b,n] x[b,n]. Two launches:
//  L1 (stm_prep): xdot -> (Ah, Al) + ||xdot||^2 ; W -> transposed (Bh, Bl);
//                 zero the per-b-tile completion counters
//  L2 (stm_mma):  HMMA GEMM, CTA tile 128x64, k-split 2, cp.async double
//                 buffer, fused bilinear epilogue -> deterministic partials;
//                 LAST of the 16 CTAs per b-tile (atomic counter election)
//                 sums the 16 fixed slots in fixed order and writes out.

#define NB 1024
#define ND 512
#define BM 128
#define BN 64
#define BKC 32            // k per chunk
#define KS 256            // k per CTA (8 chunks)
#define LDU 66            // fp32 elems per Us row

// ---------------- scratch ----------------
__device__ __nv_bfloat16 g_Ah[NB * ND];
__device__ __nv_bfloat16 g_Al[NB * ND];
__device__ __nv_bfloat16 g_Bh[ND * ND];   // [n][j] = hi(W[j][n])
__device__ __nv_bfloat16 g_Bl[ND * ND];
__device__ float g_norm[NB];
__device__ float g_partial[16 * NB];
__device__ unsigned g_ctr[8];

// smem stage layout (bytes): Ah 10240 | Al 10240 | Bh 5120 | Bl 5120 = 30720
#define ST_AH 0
#define ST_AL 10240
#define ST_BH 20480
#define ST_BL 25600
#define STAGE 30720
#define SMEM_MMA (2 * STAGE)   // 61440; Us (128*66*4=33792) reuses buf0 region

// ---------------- PTX helpers ----------------
__device__ __forceinline__ uint32_t smem_u32(const void* p) {
    uint32_t a;
    asm("{ .reg .u64 t; cvta.to.shared.u64 t, %1; cvt.u32.u64 %0, t; }"
        : "=r"(a) : "l"(p));
    return a;
}
__device__ __forceinline__ void cpa16(uint32_t dst, const void* src) {
    asm volatile("cp.async.cg.shared.global [%0], [%1], 16;\n" :: "r"(dst), "l"(src));
}
#define CP_COMMIT() asm volatile("cp.async.commit_group;\n" ::: "memory")
#define CP_WAIT(n)  asm volatile("cp.async.wait_group %0;\n" :: "n"(n) : "memory")

__device__ __forceinline__ void ldsm_x4(uint32_t& r0, uint32_t& r1,
                                        uint32_t& r2, uint32_t& r3, uint32_t addr) {
    asm volatile("ldmatrix.sync.aligned.m8n8.x4.shared.b16 {%0,%1,%2,%3}, [%4];"
                 : "=r"(r0), "=r"(r1), "=r"(r2), "=r"(r3) : "r"(addr));
}
__device__ __forceinline__ void mma16816(float* c, const uint32_t* a, const uint32_t* b) {
    asm volatile("mma.sync.aligned.m16n8k16.row.col.f32.bf16.bf16.f32 "
                 "{%0,%1,%2,%3}, {%4,%5,%6,%7}, {%8,%9}, {%0,%1,%2,%3};"
                 : "+f"(c[0]), "+f"(c[1]), "+f"(c[2]), "+f"(c[3])
                 : "r"(a[0]), "r"(a[1]), "r"(a[2]), "r"(a[3]), "r"(b[0]), "r"(b[1]));
}

// ---------------- L1: fused convert (A + norms | B transpose) ----------------
__global__ __launch_bounds__(256)
void stm_prep(const float* __restrict__ xd, const float* __restrict__ W) {
    if (blockIdx.x < 128) {
        // ---- xdot -> Ah/Al + row norms; block 0 also zeroes counters ----
        if (blockIdx.x == 0 && threadIdx.x < 8) g_ctr[threadIdx.x] = 0u;
        int wid = threadIdx.x >> 5, lane = threadIdx.x & 31;
        int b = blockIdx.x * 8 + wid;
        const float4* xr = (const float4*)(xd + (size_t)b * ND);
        __nv_bfloat162* ah = (__nv_bfloat162*)(g_Ah + (size_t)b * ND);
        __nv_bfloat162* al = (__nv_bfloat162*)(g_Al + (size_t)b * ND);
        float n2 = 0.0f;
#pragma unroll
        for (int p = 0; p < 4; p++) {
            int q = lane + 32 * p;
            float4 v = xr[q];
            n2 += v.x * v.x + v.y * v.y + v.z * v.z + v.w * v.w;
            __nv_bfloat16 hx = __float2bfloat16(v.x), hy = __float2bfloat16(v.y);
            __nv_bfloat16 hz = __float2bfloat16(v.z), hw = __float2bfloat16(v.w);
            ah[q * 2 + 0] = __halves2bfloat162(hx, hy);
            ah[q * 2 + 1] = __halves2bfloat162(hz, hw);
            al[q * 2 + 0] = __halves2bfloat162(__float2bfloat16(v.x - __bfloat162float(hx)),
                                               __float2bfloat16(v.y - __bfloat162float(hy)));
            al[q * 2 + 1] = __halves2bfloat162(__float2bfloat16(v.z - __bfloat162float(hz)),
                                               __float2bfloat16(v.w - __bfloat162float(hw)));
        }
#pragma unroll
        for (int o = 16; o > 0; o >>= 1) n2 += __shfl_xor_sync(0xffffffffu, n2, o);
        if (lane == 0) g_norm[b] = n2;
    } else {
        // ---- W -> transposed Bh/Bl (32x32 tile per block) ----
        __shared__ float s[32][33];
        int bi = blockIdx.x - 128;              // 0..255
        int n0 = (bi & 15) * 32, j0 = (bi >> 4) * 32;
        int tx = threadIdx.x & 31, ty = threadIdx.x >> 5;
#pragma unroll
        for (int i = 0; i < 4; i++) {
            int r = ty + 8 * i;
            s[r][tx] = W[(size_t)(j0 + r) * ND + n0 + tx];
        }
        __syncthreads();
#pragma unroll
        for (int i = 0; i < 4; i++) {
            int r = ty + 8 * i;                 // local n
            float v = s[tx][r];                 // = W[j0+tx][n0+r]
            __nv_bfloat16 h = __float2bfloat16(v);
            size_t o = (size_t)(n0 + r) * ND + j0 + tx;
            g_Bh[o] = h;
            g_Bl[o] = __float2bfloat16(v - __bfloat162float(h));
        }
    }
}

// ---------------- L2: HMMA GEMM + fused bilinear epilogue + finalize ----------
__device__ __forceinline__ void load_chunk(uint32_t sb, int stage, int b0, int n0,
                                           int kc, int tid) {
    uint32_t base = sb + stage * STAGE;
#pragma unroll
    for (int p = 0; p < 2; p++) {
        int idx = tid + p * 256;            // 0..511
        int row = idx >> 2, c = idx & 3;    // row 0..127, 16B chunk 0..3
        uint32_t d = base + row * 80 + c * 16;
        size_t off = (size_t)(b0 + row) * ND + kc + c * 8;
        cpa16(d + ST_AH, g_Ah + off);
        cpa16(d + ST_AL, g_Al + off);
    }
    {
        int row = tid >> 2, c = tid & 3;    // row 0..63
        uint32_t d = base + row * 80 + c * 16;
        size_t off = (size_t)(n0 + row) * ND + kc + c * 8;
        cpa16(d + ST_BH, g_Bh + off);
        cpa16(d + ST_BL, g_Bl + off);
    }
}

__global__ __launch_bounds__(256, 1)
void stm_mma(const float* __restrict__ x, float* __restrict__ out) {
    extern __shared__ __align__(128) char smem[];
    uint32_t sb = smem_u32(smem);
    const int tid = threadIdx.x, wid = tid >> 5, lane = tid & 31;
    const int wm = wid & 3, wn = wid >> 2;       // warp tile (32m x 32n)
    const int n0 = blockIdx.x * BN;
    const int b0 = blockIdx.y * BM;
    const int kz = blockIdx.z;
    const int kbase = kz * KS;

    float c[2][4][4];                             // [m16 blk][n8 blk][reg]
#pragma unroll
    for (int i = 0; i < 2; i++)
#pragma unroll
        for (int j = 0; j < 4; j++)
#pragma unroll
            for (int r = 0; r < 4; r++) c[i][j][r] = 0.0f;

    load_chunk(sb, 0, b0, n0, kbase, tid);
    CP_COMMIT();

    for (int ch = 0; ch < 8; ch++) {
        if (ch < 7) {
            load_chunk(sb, (ch + 1) & 1, b0, n0, kbase + (ch + 1) * BKC, tid);
            CP_COMMIT();
            CP_WAIT(1);
        } else {
            CP_WAIT(0);
        }
        __syncthreads();

        uint32_t st = sb + (ch & 1) * STAGE;
#pragma unroll
        for (int kk = 0; kk < BKC; kk += 16) {
            uint32_t ah[2][4], al[2][4];
#pragma unroll
            for (int mb = 0; mb < 2; mb++) {
                int row = wm * 32 + mb * 16 + (lane & 15);
                uint32_t off = row * 80 + (kk + (lane >> 4) * 8) * 2;
                ldsm_x4(ah[mb][0], ah[mb][1], ah[mb][2], ah[mb][3], st + ST_AH + off);
                ldsm_x4(al[mb][0], al[mb][1], al[mb][2], al[mb][3], st + ST_AL + off);
            }
            uint32_t bh[4][2], bl[4][2];
#pragma unroll
            for (int np = 0; np < 2; np++) {
                int row = wn * 32 + np * 16 + (lane & 7) + ((lane >> 4) << 3);
                uint32_t off = row * 80 + (kk + ((lane >> 3) & 1) * 8) * 2;
                ldsm_x4(bh[2 * np][0], bh[2 * np][1], bh[2 * np + 1][0], bh[2 * np + 1][1],
                        st + ST_BH + off);
                ldsm_x4(bl[2 * np][0], bl[2 * np][1], bl[2 * np + 1][0], bl[2 * np + 1][1],
                        st + ST_BL + off);
            }
#pragma unroll
            for (int mb = 0; mb < 2; mb++)
#pragma unroll
                for (int nb = 0; nb < 4; nb++) {
                    mma16816(c[mb][nb], ah[mb], bh[nb]);
                    mma16816(c[mb][nb], ah[mb], bl[nb]);
                    mma16816(c[mb][nb], al[mb], bh[nb]);
                }
        }
        __syncthreads();
    }

    // ---- epilogue: accumulators -> smem, per-row dot with x ----
    float* Us = (float*)smem;                     // 128 x LDU fp32 (reuses buf0)
#pragma unroll
    for (int mb = 0; mb < 2; mb++) {
        int row = wm * 32 + mb * 16 + (lane >> 2);
#pragma unroll
        for (int nb = 0; nb < 4; nb++) {
            int col = wn * 32 + nb * 8 + (lane & 3) * 2;
            *(float2*)(Us + row * LDU + col)       = make_float2(c[mb][nb][0], c[mb][nb][1]);
            *(float2*)(Us + (row + 8) * LDU + col) = make_float2(c[mb][nb][2], c[mb][nb][3]);
        }
    }
    __syncthreads();

    {
        int row = tid >> 1, half = tid & 1;       // 2 threads per row, 32 cols each
        const float4* xr = (const float4*)(x + (size_t)(b0 + row) * ND + n0 + half * 32);
        const float* ur = Us + row * LDU + half * 32;
        float s = 0.0f;
#pragma unroll
        for (int q = 0; q < 8; q++) {
            float4 v = xr[q];
            s = fmaf(ur[4 * q + 0], v.x, s);
            s = fmaf(ur[4 * q + 1], v.y, s);
            s = fmaf(ur[4 * q + 2], v.z, s);
            s = fmaf(ur[4 * q + 3], v.w, s);
        }
        s += __shfl_xor_sync(0xffffffffu, s, 1);
        if (half == 0)
            g_partial[(blockIdx.x * 2 + kz) * NB + b0 + row] = s;
    }

    // ---- fused finalize: last CTA of this b-tile sums the 16 fixed slots ----
    __threadfence();
    __shared__ unsigned s_done;
    if (tid == 0) s_done = atomicAdd(&g_ctr[blockIdx.y], 1u);
    __syncthreads();
    if (s_done == 15u) {
        __threadfence();                          // order counter read vs partial loads
        if (tid < 128) {
            int b = b0 + tid;
            float t = 0.0f;
#pragma unroll
            for (int k = 0; k < 16; k++) t += g_partial[k * NB + b];
            out[b] = g_norm[b] + t * t;
        }
    }
}

// ---------------- launch ----------------
extern "C" void kernel_launch(void* const* d_in, const int* in_sizes, int n_in,
                              void* d_out, int out_size) {
    const float* x    = (const float*)d_in[0];   // [1024, 512]
    const float* xdot = (const float*)d_in[1];   // [1024, 512]
    const float* W    = (const float*)d_in[2];   // [512, 512]
    float* out = (float*)d_out;                  // [1024]

    cudaFuncSetAttribute(stm_mma, cudaFuncAttributeMaxDynamicSharedMemorySize, SMEM_MMA);

    stm_prep<<<384, 256>>>(xdot, W);
    stm_mma<<<dim3(8, 8, 2), 256, SMEM_MMA>>>(x, out);
}